// round 4
// baseline (speedup 1.0000x reference)
#include <cuda_runtime.h>
#include <cuda_fp16.h>
#include <cuda_bf16.h>
#include <math.h>
#include <stdint.h>

#define BATCH 4
#define CDIM  256
#define CQK   32
#define NPIX  4096   // 64*64

// fp16 scratch (static device globals: allowed)
__device__ __half g_Qh[BATCH * NPIX * CQK];
__device__ __half g_Kh[BATCH * NPIX * CQK];
__device__ __half g_VhT[(size_t)BATCH * CDIM * NPIX];   // [B][C][N] transposed

// ---------------------------------------------------------------------------
// Projection kernel (fp32 compute, fp16 outputs).
// ---------------------------------------------------------------------------
__global__ __launch_bounds__(256) void proj_kernel(
    const float* __restrict__ x,
    const float* __restrict__ Wq, const float* __restrict__ bq,
    const float* __restrict__ Wk, const float* __restrict__ bk,
    const float* __restrict__ Wv, const float* __restrict__ bv)
{
    const int b  = blockIdx.y;
    const int n0 = blockIdx.x * 32;

    __shared__ float xs[32 * 260];

    const int tid = threadIdx.x;
    for (int idx = tid; idx < 32 * 256; idx += 256) {
        int i = idx & 31;
        int c = idx >> 5;
        xs[i * 260 + c] = x[(b * CDIM + c) * NPIX + n0 + i];
    }
    __syncthreads();

    const int n = tid & 31;
    const int g = tid >> 5;

    float accq[4] = {0.f, 0.f, 0.f, 0.f};
    float acck[4] = {0.f, 0.f, 0.f, 0.f};
    float accv[32];
#pragma unroll
    for (int j = 0; j < 32; j++) accv[j] = 0.f;

    const float* xrow = &xs[n * 260];

#pragma unroll 2
    for (int c = 0; c < 256; c += 4) {
        const float4 xv = *(const float4*)&xrow[c];
#pragma unroll
        for (int j = 0; j < 4; j++) {
            const float4 w = *(const float4*)&Wq[(g * 4 + j) * CDIM + c];
            accq[j] += xv.x * w.x + xv.y * w.y + xv.z * w.z + xv.w * w.w;
        }
#pragma unroll
        for (int j = 0; j < 4; j++) {
            const float4 w = *(const float4*)&Wk[(g * 4 + j) * CDIM + c];
            acck[j] += xv.x * w.x + xv.y * w.y + xv.z * w.z + xv.w * w.w;
        }
#pragma unroll
        for (int j = 0; j < 32; j++) {
            const float4 w = *(const float4*)&Wv[(g * 32 + j) * CDIM + c];
            accv[j] += xv.x * w.x + xv.y * w.y + xv.z * w.z + xv.w * w.w;
        }
    }

    const int nglob = b * NPIX + n0 + n;
#pragma unroll
    for (int j = 0; j < 4; j++) {
        g_Qh[nglob * CQK + g * 4 + j] = __float2half_rn(accq[j] + bq[g * 4 + j]);
        g_Kh[nglob * CQK + g * 4 + j] = __float2half_rn(acck[j] + bk[g * 4 + j]);
    }
#pragma unroll
    for (int j = 0; j < 32; j++) {
        g_VhT[((size_t)b * CDIM + g * 32 + j) * NPIX + n0 + n] =
            __float2half_rn(accv[j] + bv[g * 32 + j]);
    }
}

// ---------------------------------------------------------------------------
// Flash attention with mma.sync.m16n8k16 fp16 (fp32 accumulate).
// CTA: 64 queries, 256 threads (8 warps). Key tiles of 64.
// ---------------------------------------------------------------------------
#define QTILE  64
#define KTILE  64
#define QK_PAD 40   // halves per row, Qs/Ks (conflict-free fragment loads)
#define V_PAD  72   // halves per row, VsT
#define S_PAD  66   // floats per row, Ssm
#define P_PAD  70   // halves per row, Ps

// smem byte offsets
#define OFF_QS    0        // 64*40*2   = 5120
#define OFF_KS    5120     // 5120
#define OFF_VST   10240    // 256*72*2  = 36864 (also aliased as Obuf: 128*66*4)
#define OFF_SSM   47104    // 64*66*4   = 16896
#define OFF_PS    64000    // 64*70*2   = 8960
#define OFF_PMAX  72960    // 4*64*4
#define OFF_PSUM  73984    // 4*64*4
#define OFF_MS    75008    // 64*4
#define OFF_ALPHA 75264    // 64*4
#define OFF_LINV  75520    // 64*4
#define SMEM_TOTAL 75776
#define OB_PAD 66

__device__ __forceinline__ void mma16816(
    float& c0, float& c1, float& c2, float& c3,
    uint32_t a0, uint32_t a1, uint32_t a2, uint32_t a3,
    uint32_t b0, uint32_t b1)
{
    asm volatile(
        "mma.sync.aligned.m16n8k16.row.col.f32.f16.f16.f32 "
        "{%0,%1,%2,%3}, {%4,%5,%6,%7}, {%8,%9}, {%0,%1,%2,%3};\n"
        : "+f"(c0), "+f"(c1), "+f"(c2), "+f"(c3)
        : "r"(a0), "r"(a1), "r"(a2), "r"(a3), "r"(b0), "r"(b1));
}

__global__ __launch_bounds__(256, 2) void attn_kernel(
    float* __restrict__ out, const float* __restrict__ gamma)
{
    extern __shared__ char sm[];
    __half* Qs    = (__half*)(sm + OFF_QS);
    __half* Ks    = (__half*)(sm + OFF_KS);
    __half* VsT   = (__half*)(sm + OFF_VST);
    float*  Ssm   = (float*)(sm + OFF_SSM);
    __half* Ps    = (__half*)(sm + OFF_PS);
    float*  pmax  = (float*)(sm + OFF_PMAX);
    float*  psum  = (float*)(sm + OFF_PSUM);
    float*  m_s   = (float*)(sm + OFF_MS);
    float*  alp_s = (float*)(sm + OFF_ALPHA);
    float*  linv  = (float*)(sm + OFF_LINV);
    float*  Obuf  = (float*)(sm + OFF_VST);   // alias, used only in epilogue

    const int b   = blockIdx.y;
    const int q0  = blockIdx.x * QTILE;
    const int tid = threadIdx.x;
    const int w   = tid >> 5;
    const int lane = tid & 31;
    const int g = lane >> 2;   // mma groupID
    const int t = lane & 3;    // thread-in-group

    const size_t bN = (size_t)b * NPIX;

    // QK-phase warp mapping: S rows 16*(w&3), cols 32*(w>>2)
    const int qk_rb = 16 * (w & 3);
    const int qk_cb = 32 * (w >> 2);
    // PV-phase warp mapping: out rows 32*(w&1), cols 64*(w>>1)
    const int pv_qb = 32 * (w & 1);
    const int pv_cb = 64 * (w >> 1);

    // softmax mapping
    const int sq   = tid & 63;
    const int part = tid >> 6;

    // Load Q tile once: 64 rows x 32 halves
    {
        int row = tid >> 2, seg = tid & 3;
        *(uint4*)&Qs[row * QK_PAD + seg * 8] =
            *(const uint4*)&g_Qh[(bN + q0 + row) * CQK + seg * 8];
    }
    __syncthreads();

    // Preload Q fragments (persistent across all key tiles)
    uint32_t qa[2][4];
#pragma unroll
    for (int s = 0; s < 2; s++) {
        const __half* base = &Qs[(qk_rb + g) * QK_PAD + 2 * t + 16 * s];
        qa[s][0] = *(const uint32_t*)base;
        qa[s][2] = *(const uint32_t*)(base + 8);
        const __half* b8 = base + 8 * QK_PAD;
        qa[s][1] = *(const uint32_t*)b8;
        qa[s][3] = *(const uint32_t*)(b8 + 8);
    }

    float acc[2][8][4];
#pragma unroll
    for (int i = 0; i < 2; i++)
#pragma unroll
        for (int j = 0; j < 8; j++)
#pragma unroll
            for (int k = 0; k < 4; k++) acc[i][j][k] = 0.f;

    float m_run = -INFINITY, l_run = 0.f, alpha_reg = 0.f;

    for (int kt = 0; kt < NPIX / KTILE; kt++) {
        const int m0 = kt * KTILE;
        __syncthreads();   // previous iter's PV reads done before overwriting tiles

        // Load K tile: 64 x 32 halves
        {
            int row = tid >> 2, seg = tid & 3;
            *(uint4*)&Ks[row * QK_PAD + seg * 8] =
                *(const uint4*)&g_Kh[(bN + m0 + row) * CQK + seg * 8];
        }
        // Load V^T tile: 256 rows (c) x 64 halves (m)
#pragma unroll
        for (int it = 0; it < 16; it++) {
            int idx = tid + 256 * it;
            int c = idx >> 4, sg2 = idx & 15;
            *(uint2*)&VsT[c * V_PAD + sg2 * 4] =
                *(const uint2*)&g_VhT[((size_t)b * CDIM + c) * NPIX + m0 + sg2 * 4];
        }
        __syncthreads();

        // --- S = Q K^T (each warp: 16x32 region = 4 n-tiles x 2 k-steps) ---
#pragma unroll
        for (int j = 0; j < 4; j++) {
            float c0 = 0.f, c1 = 0.f, c2 = 0.f, c3 = 0.f;
#pragma unroll
            for (int s = 0; s < 2; s++) {
                const __half* kb = &Ks[(qk_cb + 8 * j + g) * QK_PAD + 2 * t + 16 * s];
                uint32_t b0 = *(const uint32_t*)kb;
                uint32_t b1 = *(const uint32_t*)(kb + 8);
                mma16816(c0, c1, c2, c3, qa[s][0], qa[s][1], qa[s][2], qa[s][3], b0, b1);
            }
            float* srow = &Ssm[(qk_rb + g) * S_PAD + qk_cb + 8 * j + 2 * t];
            srow[0] = c0; srow[1] = c1;
            srow += 8 * S_PAD;
            srow[0] = c2; srow[1] = c3;
        }
        __syncthreads();

        // --- online softmax: 4 partial threads per query row ---
        float lm = -INFINITY;
#pragma unroll
        for (int i = 0; i < 16; i++)
            lm = fmaxf(lm, Ssm[sq * S_PAD + part * 16 + i]);
        pmax[part * 64 + sq] = lm;
        __syncthreads();

        if (tid < 64) {
            float tm = fmaxf(fmaxf(pmax[tid], pmax[64 + tid]),
                             fmaxf(pmax[128 + tid], pmax[192 + tid]));
            float mnew = fmaxf(m_run, tm);
            alpha_reg = __expf(m_run - mnew);
            m_run = mnew;
            m_s[tid]   = mnew;
            alp_s[tid] = alpha_reg;
        }
        __syncthreads();

        {
            const float mn = m_s[sq];
            float ps = 0.f;
#pragma unroll
            for (int i = 0; i < 16; i += 2) {
                float p0 = __expf(Ssm[sq * S_PAD + part * 16 + i]     - mn);
                float p1 = __expf(Ssm[sq * S_PAD + part * 16 + i + 1] - mn);
                ps += p0 + p1;
                *(__half2*)&Ps[sq * P_PAD + part * 16 + i] = __floats2half2_rn(p0, p1);
            }
            psum[part * 64 + sq] = ps;
        }
        __syncthreads();

        if (tid < 64)
            l_run = l_run * alpha_reg
                  + psum[tid] + psum[64 + tid] + psum[128 + tid] + psum[192 + tid];

        // --- PV: rescale accumulators, then O += P V ---
        const float al0 = alp_s[pv_qb + g];
        const float al1 = alp_s[pv_qb + 8 + g];
        const float al2 = alp_s[pv_qb + 16 + g];
        const float al3 = alp_s[pv_qb + 24 + g];
#pragma unroll
        for (int j = 0; j < 8; j++) {
            acc[0][j][0] *= al0; acc[0][j][1] *= al0;
            acc[0][j][2] *= al1; acc[0][j][3] *= al1;
            acc[1][j][0] *= al2; acc[1][j][1] *= al2;
            acc[1][j][2] *= al3; acc[1][j][3] *= al3;
        }

#pragma unroll
        for (int s = 0; s < 4; s++) {
            uint32_t pa[2][4];
#pragma unroll
            for (int i = 0; i < 2; i++) {
                const __half* pb = &Ps[(pv_qb + 16 * i + g) * P_PAD + 2 * t + 16 * s];
                pa[i][0] = *(const uint32_t*)pb;
                pa[i][2] = *(const uint32_t*)(pb + 8);
                const __half* p8 = pb + 8 * P_PAD;
                pa[i][1] = *(const uint32_t*)p8;
                pa[i][3] = *(const uint32_t*)(p8 + 8);
            }
#pragma unroll
            for (int j = 0; j < 8; j++) {
                const __half* vb = &VsT[(pv_cb + 8 * j + g) * V_PAD + 2 * t + 16 * s];
                uint32_t b0 = *(const uint32_t*)vb;
                uint32_t b1 = *(const uint32_t*)(vb + 8);
                mma16816(acc[0][j][0], acc[0][j][1], acc[0][j][2], acc[0][j][3],
                         pa[0][0], pa[0][1], pa[0][2], pa[0][3], b0, b1);
                mma16816(acc[1][j][0], acc[1][j][1], acc[1][j][2], acc[1][j][3],
                         pa[1][0], pa[1][1], pa[1][2], pa[1][3], b0, b1);
            }
        }
    }

    // --- epilogue: scale by gamma / l, transpose through smem, store coalesced ---
    if (tid < 64) linv[tid] = 1.f / l_run;
    const float gamma0 = gamma[0];

#pragma unroll
    for (int h = 0; h < 2; h++) {
        __syncthreads();
        if ((pv_cb >> 7) == h) {
            const int cl = pv_cb & 127;
#pragma unroll
            for (int i = 0; i < 2; i++) {
                const int r0 = pv_qb + 16 * i + g;
                const int r1 = r0 + 8;
                const float s0 = linv[r0] * gamma0;
                const float s1 = linv[r1] * gamma0;
#pragma unroll
                for (int j = 0; j < 8; j++) {
                    const int c = cl + 8 * j + 2 * t;
                    Obuf[c * OB_PAD + r0]       = acc[i][j][0] * s0;
                    Obuf[(c + 1) * OB_PAD + r0] = acc[i][j][1] * s0;
                    Obuf[c * OB_PAD + r1]       = acc[i][j][2] * s1;
                    Obuf[(c + 1) * OB_PAD + r1] = acc[i][j][3] * s1;
                }
            }
        }
        __syncthreads();
#pragma unroll
        for (int it = 0; it < 32; it++) {
            int idx = tid + 256 * it;
            int c = idx >> 6, q = idx & 63;
            out[((size_t)b * CDIM + h * 128 + c) * NPIX + q0 + q] = Obuf[c * OB_PAD + q];
        }
    }
}

// ---------------------------------------------------------------------------
// Inputs: x, Wq, bq, Wk, bk, Wv, bv, gamma. Output: float32 [B,C,H,W].
// ---------------------------------------------------------------------------
extern "C" void kernel_launch(void* const* d_in, const int* in_sizes, int n_in,
                              void* d_out, int out_size)
{
    const float* x     = (const float*)d_in[0];
    const float* Wq    = (const float*)d_in[1];
    const float* bq    = (const float*)d_in[2];
    const float* Wk    = (const float*)d_in[3];
    const float* bk    = (const float*)d_in[4];
    const float* Wv    = (const float*)d_in[5];
    const float* bv    = (const float*)d_in[6];
    const float* gamma = (const float*)d_in[7];
    float* out = (float*)d_out;

    // Opt in to >48KB dynamic smem (idempotent; persists across calls)
    cudaFuncSetAttribute(attn_kernel,
                         cudaFuncAttributeMaxDynamicSharedMemorySize, SMEM_TOTAL);

    proj_kernel<<<dim3(NPIX / 32, BATCH), 256>>>(x, Wq, bq, Wk, bk, Wv, bv);
    attn_kernel<<<dim3(NPIX / QTILE, BATCH), 256, SMEM_TOTAL>>>(out, gamma);
}

// round 5
// speedup vs baseline: 1.5973x; 1.5973x over previous
#include <cuda_runtime.h>
#include <cuda_fp16.h>
#include <cuda_bf16.h>
#include <math.h>
#include <stdint.h>

#define BATCH 4
#define CDIM  256
#define CQK   32
#define NPIX  4096   // 64*64
#define MROWS 320    // 32 (Q) + 32 (K) + 256 (V)

// fp16 scratch (static device globals: allowed)
__device__ __half g_Qh[BATCH * NPIX * CQK];
__device__ __half g_Kh[BATCH * NPIX * CQK];
__device__ __half g_VhT[(size_t)BATCH * CDIM * NPIX];   // [B][C][N]
__device__ __half g_xhT[(size_t)BATCH * NPIX * CDIM];   // [B][N][C]
__device__ __half g_Wh[MROWS * CDIM];                   // Wq|Wk|Wv stacked
__device__ float  g_ball[MROWS];

// ---------------------------------------------------------------------------
// Weight + bias convert: g_Wh[320][256] fp16, g_ball[320] fp32.
// ---------------------------------------------------------------------------
__global__ void wconv_kernel(
    const float* __restrict__ Wq, const float* __restrict__ bq,
    const float* __restrict__ Wk, const float* __restrict__ bk,
    const float* __restrict__ Wv, const float* __restrict__ bv)
{
    const int gid = blockIdx.x * 256 + threadIdx.x;
    for (int i = gid; i < MROWS * CDIM; i += gridDim.x * 256) {
        const int row = i >> 8, col = i & 255;
        float v;
        if (row < 32)       v = Wq[row * CDIM + col];
        else if (row < 64)  v = Wk[(row - 32) * CDIM + col];
        else                v = Wv[(row - 64) * CDIM + col];
        g_Wh[i] = __float2half_rn(v);
    }
    if (gid < MROWS) {
        g_ball[gid] = (gid < 32) ? bq[gid] : (gid < 64) ? bk[gid - 32] : bv[gid - 64];
    }
}

// ---------------------------------------------------------------------------
// x transpose+convert: x [B][C][N] fp32 -> g_xhT [B][N][C] fp16 (32x32 tiles).
// ---------------------------------------------------------------------------
__global__ __launch_bounds__(256) void xconv_kernel(const float* __restrict__ x)
{
    __shared__ __half ts[32 * 40];
    const int b  = blockIdx.z;
    const int c0 = blockIdx.y * 32;
    const int n0 = blockIdx.x * 32;
    const int tid = threadIdx.x;

#pragma unroll
    for (int it = 0; it < 4; it++) {
        const int idx = tid + 256 * it;
        const int cr = idx >> 5, nc = idx & 31;
        ts[nc * 40 + cr] =
            __float2half_rn(x[((size_t)b * CDIM + c0 + cr) * NPIX + n0 + nc]);
    }
    __syncthreads();
    if (tid < 128) {
        const int r = tid >> 2, sg = tid & 3;
        *(uint4*)&g_xhT[((size_t)b * NPIX + n0 + r) * CDIM + c0 + sg * 8] =
            *(const uint4*)&ts[r * 40 + sg * 8];
    }
}

// ---------------------------------------------------------------------------
// Projection GEMM (fp16 HMMA, fp32 acc): out[m][n] = sum_k W[m][k] * xT[n][k].
// CTA tile 64(m) x 128(n), k-chunks of 64. grid (N/128, B, 5).
// m in [0,64): Q|K rows -> transpose epilogue to g_Qh/g_Kh [n][32].
// m in [64,320): V rows -> direct store to g_VhT [c][n].
// Fragment addressing identical to the validated attn_kernel patterns.
// ---------------------------------------------------------------------------
#define GP 72   // padded row length (halves) for Wa/Xb: 36 words, conflict-free frags

__device__ __forceinline__ void mma16816(
    float& c0, float& c1, float& c2, float& c3,
    uint32_t a0, uint32_t a1, uint32_t a2, uint32_t a3,
    uint32_t b0, uint32_t b1)
{
    asm volatile(
        "mma.sync.aligned.m16n8k16.row.col.f32.f16.f16.f32 "
        "{%0,%1,%2,%3}, {%4,%5,%6,%7}, {%8,%9}, {%0,%1,%2,%3};\n"
        : "+f"(c0), "+f"(c1), "+f"(c2), "+f"(c3)
        : "r"(a0), "r"(a1), "r"(a2), "r"(a3), "r"(b0), "r"(b1));
}

__global__ __launch_bounds__(256, 2) void proj_gemm_kernel()
{
    __shared__ __align__(16) char smraw[(64 + 128) * GP * 2];
    __half* Wa = (__half*)smraw;                    // [64][GP]
    __half* Xb = (__half*)(smraw + 64 * GP * 2);    // [128][GP]; epilogue: Obuf [128][GP]

    const int n0 = blockIdx.x * 128;
    const int b  = blockIdx.y;
    const int m0 = blockIdx.z * 64;
    const int tid = threadIdx.x;
    const int w = tid >> 5, lane = tid & 31;
    const int g = lane >> 2, t = lane & 3;
    const int mw = 32 * (w & 1);
    const int nw = 32 * (w >> 1);

    float acc[2][4][4];
#pragma unroll
    for (int i = 0; i < 2; i++)
#pragma unroll
        for (int j = 0; j < 4; j++)
#pragma unroll
            for (int k = 0; k < 4; k++) acc[i][j][k] = 0.f;

    for (int kc = 0; kc < 4; kc++) {
        __syncthreads();
        // Load W tile: 64 rows x 64 halves
#pragma unroll
        for (int r = 0; r < 2; r++) {
            const int idx = tid + 256 * r;
            const int row = idx >> 3, seg = idx & 7;
            *(uint4*)&Wa[row * GP + seg * 8] =
                *(const uint4*)&g_Wh[(m0 + row) * CDIM + kc * 64 + seg * 8];
        }
        // Load xT tile: 128 rows x 64 halves
#pragma unroll
        for (int r = 0; r < 4; r++) {
            const int idx = tid + 256 * r;
            const int row = idx >> 3, seg = idx & 7;
            *(uint4*)&Xb[row * GP + seg * 8] =
                *(const uint4*)&g_xhT[((size_t)b * NPIX + n0 + row) * CDIM + kc * 64 + seg * 8];
        }
        __syncthreads();

#pragma unroll
        for (int s = 0; s < 4; s++) {
            uint32_t a[2][4];
#pragma unroll
            for (int i = 0; i < 2; i++) {
                const __half* base = &Wa[(mw + 16 * i + g) * GP + 2 * t + 16 * s];
                a[i][0] = *(const uint32_t*)base;
                a[i][2] = *(const uint32_t*)(base + 8);
                const __half* b8 = base + 8 * GP;
                a[i][1] = *(const uint32_t*)b8;
                a[i][3] = *(const uint32_t*)(b8 + 8);
            }
#pragma unroll
            for (int j = 0; j < 4; j++) {
                const __half* kb = &Xb[(nw + 8 * j + g) * GP + 2 * t + 16 * s];
                const uint32_t b0 = *(const uint32_t*)kb;
                const uint32_t b1 = *(const uint32_t*)(kb + 8);
                mma16816(acc[0][j][0], acc[0][j][1], acc[0][j][2], acc[0][j][3],
                         a[0][0], a[0][1], a[0][2], a[0][3], b0, b1);
                mma16816(acc[1][j][0], acc[1][j][1], acc[1][j][2], acc[1][j][3],
                         a[1][0], a[1][1], a[1][2], a[1][3], b0, b1);
            }
        }
    }

    if (m0 >= 64) {
        // ---- V epilogue: direct store, g_VhT[c][n], c = m0-64+row ----
#pragma unroll
        for (int i = 0; i < 2; i++) {
            const int r0 = mw + 16 * i + g;
            const int r1 = r0 + 8;
            const float bb0 = g_ball[m0 + r0];
            const float bb1 = g_ball[m0 + r1];
            const size_t c0g = (size_t)b * CDIM + (m0 - 64 + r0);
            const size_t c1g = (size_t)b * CDIM + (m0 - 64 + r1);
#pragma unroll
            for (int j = 0; j < 4; j++) {
                const int n = n0 + nw + 8 * j + 2 * t;
                *(__half2*)&g_VhT[c0g * NPIX + n] =
                    __floats2half2_rn(acc[i][j][0] + bb0, acc[i][j][1] + bb0);
                *(__half2*)&g_VhT[c1g * NPIX + n] =
                    __floats2half2_rn(acc[i][j][2] + bb1, acc[i][j][3] + bb1);
            }
        }
    } else {
        // ---- Q/K epilogue: transpose via smem (Obuf aliases Xb), then copy ----
        __half* Obuf = Xb;   // [128 n][GP m]
        __syncthreads();     // all warps done reading Xb fragments
#pragma unroll
        for (int i = 0; i < 2; i++) {
            const int r0 = mw + 16 * i + g;
            const int r1 = r0 + 8;
            const float bb0 = g_ball[r0];
            const float bb1 = g_ball[r1];
#pragma unroll
            for (int j = 0; j < 4; j++) {
                const int n = nw + 8 * j + 2 * t;
                Obuf[n * GP + r0]       = __float2half_rn(acc[i][j][0] + bb0);
                Obuf[(n + 1) * GP + r0] = __float2half_rn(acc[i][j][1] + bb0);
                Obuf[n * GP + r1]       = __float2half_rn(acc[i][j][2] + bb1);
                Obuf[(n + 1) * GP + r1] = __float2half_rn(acc[i][j][3] + bb1);
            }
        }
        __syncthreads();
#pragma unroll
        for (int r = 0; r < 2; r++) {
            const int idx = tid + 256 * r;
            const int n = idx >> 2, seg = idx & 3;
            // Q: m 0..31
            *(uint4*)&g_Qh[((size_t)b * NPIX + n0 + n) * CQK + seg * 8] =
                *(const uint4*)&Obuf[n * GP + seg * 8];
            // K: m 32..63
            *(uint4*)&g_Kh[((size_t)b * NPIX + n0 + n) * CQK + seg * 8] =
                *(const uint4*)&Obuf[n * GP + 32 + seg * 8];
        }
    }
}

// ---------------------------------------------------------------------------
// Flash attention with mma.sync.m16n8k16 fp16 (fp32 accumulate). UNCHANGED.
// CTA: 64 queries, 256 threads (8 warps). Key tiles of 64.
// ---------------------------------------------------------------------------
#define QTILE  64
#define KTILE  64
#define QK_PAD 40
#define V_PAD  72
#define S_PAD  66
#define P_PAD  70

#define OFF_QS    0
#define OFF_KS    5120
#define OFF_VST   10240
#define OFF_SSM   47104
#define OFF_PS    64000
#define OFF_PMAX  72960
#define OFF_PSUM  73984
#define OFF_MS    75008
#define OFF_ALPHA 75264
#define OFF_LINV  75520
#define SMEM_TOTAL 75776
#define OB_PAD 66

__global__ __launch_bounds__(256, 2) void attn_kernel(
    float* __restrict__ out, const float* __restrict__ gamma)
{
    extern __shared__ char sm[];
    __half* Qs    = (__half*)(sm + OFF_QS);
    __half* Ks    = (__half*)(sm + OFF_KS);
    __half* VsT   = (__half*)(sm + OFF_VST);
    float*  Ssm   = (float*)(sm + OFF_SSM);
    __half* Ps    = (__half*)(sm + OFF_PS);
    float*  pmax  = (float*)(sm + OFF_PMAX);
    float*  psum  = (float*)(sm + OFF_PSUM);
    float*  m_s   = (float*)(sm + OFF_MS);
    float*  alp_s = (float*)(sm + OFF_ALPHA);
    float*  linv  = (float*)(sm + OFF_LINV);
    float*  Obuf  = (float*)(sm + OFF_VST);

    const int b   = blockIdx.y;
    const int q0  = blockIdx.x * QTILE;
    const int tid = threadIdx.x;
    const int w   = tid >> 5;
    const int lane = tid & 31;
    const int g = lane >> 2;
    const int t = lane & 3;

    const size_t bN = (size_t)b * NPIX;

    const int qk_rb = 16 * (w & 3);
    const int qk_cb = 32 * (w >> 2);
    const int pv_qb = 32 * (w & 1);
    const int pv_cb = 64 * (w >> 1);

    const int sq   = tid & 63;
    const int part = tid >> 6;

    {
        int row = tid >> 2, seg = tid & 3;
        *(uint4*)&Qs[row * QK_PAD + seg * 8] =
            *(const uint4*)&g_Qh[(bN + q0 + row) * CQK + seg * 8];
    }
    __syncthreads();

    uint32_t qa[2][4];
#pragma unroll
    for (int s = 0; s < 2; s++) {
        const __half* base = &Qs[(qk_rb + g) * QK_PAD + 2 * t + 16 * s];
        qa[s][0] = *(const uint32_t*)base;
        qa[s][2] = *(const uint32_t*)(base + 8);
        const __half* b8 = base + 8 * QK_PAD;
        qa[s][1] = *(const uint32_t*)b8;
        qa[s][3] = *(const uint32_t*)(b8 + 8);
    }

    float acc[2][8][4];
#pragma unroll
    for (int i = 0; i < 2; i++)
#pragma unroll
        for (int j = 0; j < 8; j++)
#pragma unroll
            for (int k = 0; k < 4; k++) acc[i][j][k] = 0.f;

    float m_run = -INFINITY, l_run = 0.f, alpha_reg = 0.f;

    for (int kt = 0; kt < NPIX / KTILE; kt++) {
        const int m0 = kt * KTILE;
        __syncthreads();

        {
            int row = tid >> 2, seg = tid & 3;
            *(uint4*)&Ks[row * QK_PAD + seg * 8] =
                *(const uint4*)&g_Kh[(bN + m0 + row) * CQK + seg * 8];
        }
#pragma unroll
        for (int it = 0; it < 16; it++) {
            int idx = tid + 256 * it;
            int c = idx >> 4, sg2 = idx & 15;
            *(uint2*)&VsT[c * V_PAD + sg2 * 4] =
                *(const uint2*)&g_VhT[((size_t)b * CDIM + c) * NPIX + m0 + sg2 * 4];
        }
        __syncthreads();

#pragma unroll
        for (int j = 0; j < 4; j++) {
            float c0 = 0.f, c1 = 0.f, c2 = 0.f, c3 = 0.f;
#pragma unroll
            for (int s = 0; s < 2; s++) {
                const __half* kb = &Ks[(qk_cb + 8 * j + g) * QK_PAD + 2 * t + 16 * s];
                uint32_t b0 = *(const uint32_t*)kb;
                uint32_t b1 = *(const uint32_t*)(kb + 8);
                mma16816(c0, c1, c2, c3, qa[s][0], qa[s][1], qa[s][2], qa[s][3], b0, b1);
            }
            float* srow = &Ssm[(qk_rb + g) * S_PAD + qk_cb + 8 * j + 2 * t];
            srow[0] = c0; srow[1] = c1;
            srow += 8 * S_PAD;
            srow[0] = c2; srow[1] = c3;
        }
        __syncthreads();

        float lm = -INFINITY;
#pragma unroll
        for (int i = 0; i < 16; i++)
            lm = fmaxf(lm, Ssm[sq * S_PAD + part * 16 + i]);
        pmax[part * 64 + sq] = lm;
        __syncthreads();

        if (tid < 64) {
            float tm = fmaxf(fmaxf(pmax[tid], pmax[64 + tid]),
                             fmaxf(pmax[128 + tid], pmax[192 + tid]));
            float mnew = fmaxf(m_run, tm);
            alpha_reg = __expf(m_run - mnew);
            m_run = mnew;
            m_s[tid]   = mnew;
            alp_s[tid] = alpha_reg;
        }
        __syncthreads();

        {
            const float mn = m_s[sq];
            float ps = 0.f;
#pragma unroll
            for (int i = 0; i < 16; i += 2) {
                float p0 = __expf(Ssm[sq * S_PAD + part * 16 + i]     - mn);
                float p1 = __expf(Ssm[sq * S_PAD + part * 16 + i + 1] - mn);
                ps += p0 + p1;
                *(__half2*)&Ps[sq * P_PAD + part * 16 + i] = __floats2half2_rn(p0, p1);
            }
            psum[part * 64 + sq] = ps;
        }
        __syncthreads();

        if (tid < 64)
            l_run = l_run * alpha_reg
                  + psum[tid] + psum[64 + tid] + psum[128 + tid] + psum[192 + tid];

        const float al0 = alp_s[pv_qb + g];
        const float al1 = alp_s[pv_qb + 8 + g];
        const float al2 = alp_s[pv_qb + 16 + g];
        const float al3 = alp_s[pv_qb + 24 + g];
#pragma unroll
        for (int j = 0; j < 8; j++) {
            acc[0][j][0] *= al0; acc[0][j][1] *= al0;
            acc[0][j][2] *= al1; acc[0][j][3] *= al1;
            acc[1][j][0] *= al2; acc[1][j][1] *= al2;
            acc[1][j][2] *= al3; acc[1][j][3] *= al3;
        }

#pragma unroll
        for (int s = 0; s < 4; s++) {
            uint32_t pa[2][4];
#pragma unroll
            for (int i = 0; i < 2; i++) {
                const __half* pb = &Ps[(pv_qb + 16 * i + g) * P_PAD + 2 * t + 16 * s];
                pa[i][0] = *(const uint32_t*)pb;
                pa[i][2] = *(const uint32_t*)(pb + 8);
                const __half* p8 = pb + 8 * P_PAD;
                pa[i][1] = *(const uint32_t*)p8;
                pa[i][3] = *(const uint32_t*)(p8 + 8);
            }
#pragma unroll
            for (int j = 0; j < 8; j++) {
                const __half* vb = &VsT[(pv_cb + 8 * j + g) * V_PAD + 2 * t + 16 * s];
                uint32_t b0 = *(const uint32_t*)vb;
                uint32_t b1 = *(const uint32_t*)(vb + 8);
                mma16816(acc[0][j][0], acc[0][j][1], acc[0][j][2], acc[0][j][3],
                         pa[0][0], pa[0][1], pa[0][2], pa[0][3], b0, b1);
                mma16816(acc[1][j][0], acc[1][j][1], acc[1][j][2], acc[1][j][3],
                         pa[1][0], pa[1][1], pa[1][2], pa[1][3], b0, b1);
            }
        }
    }

    if (tid < 64) linv[tid] = 1.f / l_run;
    const float gamma0 = gamma[0];

#pragma unroll
    for (int h = 0; h < 2; h++) {
        __syncthreads();
        if ((pv_cb >> 7) == h) {
            const int cl = pv_cb & 127;
#pragma unroll
            for (int i = 0; i < 2; i++) {
                const int r0 = pv_qb + 16 * i + g;
                const int r1 = r0 + 8;
                const float s0 = linv[r0] * gamma0;
                const float s1 = linv[r1] * gamma0;
#pragma unroll
                for (int j = 0; j < 8; j++) {
                    const int c = cl + 8 * j + 2 * t;
                    Obuf[c * OB_PAD + r0]       = acc[i][j][0] * s0;
                    Obuf[(c + 1) * OB_PAD + r0] = acc[i][j][1] * s0;
                    Obuf[c * OB_PAD + r1]       = acc[i][j][2] * s1;
                    Obuf[(c + 1) * OB_PAD + r1] = acc[i][j][3] * s1;
                }
            }
        }
        __syncthreads();
#pragma unroll
        for (int it = 0; it < 32; it++) {
            int idx = tid + 256 * it;
            int c = idx >> 6, q = idx & 63;
            out[((size_t)b * CDIM + h * 128 + c) * NPIX + q0 + q] = Obuf[c * OB_PAD + q];
        }
    }
}

// ---------------------------------------------------------------------------
// Inputs: x, Wq, bq, Wk, bk, Wv, bv, gamma. Output: float32 [B,C,H,W].
// ---------------------------------------------------------------------------
extern "C" void kernel_launch(void* const* d_in, const int* in_sizes, int n_in,
                              void* d_out, int out_size)
{
    const float* x     = (const float*)d_in[0];
    const float* Wq    = (const float*)d_in[1];
    const float* bq    = (const float*)d_in[2];
    const float* Wk    = (const float*)d_in[3];
    const float* bk    = (const float*)d_in[4];
    const float* Wv    = (const float*)d_in[5];
    const float* bv    = (const float*)d_in[6];
    const float* gamma = (const float*)d_in[7];
    float* out = (float*)d_out;

    cudaFuncSetAttribute(attn_kernel,
                         cudaFuncAttributeMaxDynamicSharedMemorySize, SMEM_TOTAL);

    wconv_kernel<<<80, 256>>>(Wq, bq, Wk, bk, Wv, bv);
    xconv_kernel<<<dim3(NPIX / 32, CDIM / 32, BATCH), 256>>>(x);
    proj_gemm_kernel<<<dim3(NPIX / 128, BATCH, 5), 256>>>();
    attn_kernel<<<dim3(NPIX / QTILE, BATCH), 256, SMEM_TOTAL>>>(out, gamma);
}

// round 7
// speedup vs baseline: 1.8615x; 1.1654x over previous
#include <cuda_runtime.h>
#include <cuda_fp16.h>
#include <cuda_bf16.h>
#include <math.h>
#include <stdint.h>

#define BATCH 4
#define CDIM  256
#define CQK   32
#define NPIX  4096   // 64*64
#define MROWS 320    // 32 (Q) + 32 (K) + 256 (V)

// fp16 scratch (static device globals: allowed)
__device__ __half g_Qh[BATCH * NPIX * CQK];
__device__ __half g_Kh[BATCH * NPIX * CQK];
__device__ __half g_VhT[(size_t)BATCH * CDIM * NPIX];   // [B][C][N]
__device__ __half g_xhT[(size_t)BATCH * NPIX * CDIM];   // [B][N][C]
__device__ __half g_Wh[MROWS * CDIM];                   // Wq|Wk|Wv stacked
__device__ float  g_ball[MROWS];

// ---------------------------------------------------------------------------
// helpers (defined BEFORE all uses)
// ---------------------------------------------------------------------------
__device__ __forceinline__ uint32_t h2_as_u32(__half2 h)
{
    return *(uint32_t*)&h;
}

__device__ __forceinline__ void mma16816(
    float& c0, float& c1, float& c2, float& c3,
    uint32_t a0, uint32_t a1, uint32_t a2, uint32_t a3,
    uint32_t b0, uint32_t b1)
{
    asm volatile(
        "mma.sync.aligned.m16n8k16.row.col.f32.f16.f16.f32 "
        "{%0,%1,%2,%3}, {%4,%5,%6,%7}, {%8,%9}, {%0,%1,%2,%3};\n"
        : "+f"(c0), "+f"(c1), "+f"(c2), "+f"(c3)
        : "r"(a0), "r"(a1), "r"(a2), "r"(a3), "r"(b0), "r"(b1));
}

__device__ __forceinline__ void cpa16(uint32_t dst, const void* src)
{
    asm volatile("cp.async.cg.shared.global [%0], [%1], 16;\n" :: "r"(dst), "l"(src));
}
__device__ __forceinline__ void cpa_commit()
{
    asm volatile("cp.async.commit_group;\n" ::: "memory");
}
__device__ __forceinline__ void cpa_wait0()
{
    asm volatile("cp.async.wait_group 0;\n" ::: "memory");
}

// ---------------------------------------------------------------------------
// Weight + bias convert.
// ---------------------------------------------------------------------------
__global__ void wconv_kernel(
    const float* __restrict__ Wq, const float* __restrict__ bq,
    const float* __restrict__ Wk, const float* __restrict__ bk,
    const float* __restrict__ Wv, const float* __restrict__ bv)
{
    const int gid = blockIdx.x * 256 + threadIdx.x;
    for (int i = gid; i < MROWS * CDIM; i += gridDim.x * 256) {
        const int row = i >> 8, col = i & 255;
        float v;
        if (row < 32)       v = Wq[row * CDIM + col];
        else if (row < 64)  v = Wk[(row - 32) * CDIM + col];
        else                v = Wv[(row - 64) * CDIM + col];
        g_Wh[i] = __float2half_rn(v);
    }
    if (gid < MROWS) {
        g_ball[gid] = (gid < 32) ? bq[gid] : (gid < 64) ? bk[gid - 32] : bv[gid - 64];
    }
}

// ---------------------------------------------------------------------------
// x transpose+convert: x [B][C][N] fp32 -> g_xhT [B][N][C] fp16.
// ---------------------------------------------------------------------------
__global__ __launch_bounds__(256) void xconv_kernel(const float* __restrict__ x)
{
    __shared__ __half ts[32 * 40];
    const int b  = blockIdx.z;
    const int c0 = blockIdx.y * 32;
    const int n0 = blockIdx.x * 32;
    const int tid = threadIdx.x;

#pragma unroll
    for (int it = 0; it < 4; it++) {
        const int idx = tid + 256 * it;
        const int cr = idx >> 5, nc = idx & 31;
        ts[nc * 40 + cr] =
            __float2half_rn(x[((size_t)b * CDIM + c0 + cr) * NPIX + n0 + nc]);
    }
    __syncthreads();
    if (tid < 128) {
        const int r = tid >> 2, sg = tid & 3;
        *(uint4*)&g_xhT[((size_t)b * NPIX + n0 + r) * CDIM + c0 + sg * 8] =
            *(const uint4*)&ts[r * 40 + sg * 8];
    }
}

// ---------------------------------------------------------------------------
// Projection GEMM (fp16 HMMA, fp32 acc).
// ---------------------------------------------------------------------------
#define GP 72

__global__ __launch_bounds__(256, 2) void proj_gemm_kernel()
{
    __shared__ __align__(16) char smraw[(64 + 128) * GP * 2];
    __half* Wa = (__half*)smraw;
    __half* Xb = (__half*)(smraw + 64 * GP * 2);

    const int n0 = blockIdx.x * 128;
    const int b  = blockIdx.y;
    const int m0 = blockIdx.z * 64;
    const int tid = threadIdx.x;
    const int w = tid >> 5, lane = tid & 31;
    const int g = lane >> 2, t = lane & 3;
    const int mw = 32 * (w & 1);
    const int nw = 32 * (w >> 1);

    float acc[2][4][4];
#pragma unroll
    for (int i = 0; i < 2; i++)
#pragma unroll
        for (int j = 0; j < 4; j++)
#pragma unroll
            for (int k = 0; k < 4; k++) acc[i][j][k] = 0.f;

    for (int kc = 0; kc < 4; kc++) {
        __syncthreads();
#pragma unroll
        for (int r = 0; r < 2; r++) {
            const int idx = tid + 256 * r;
            const int row = idx >> 3, seg = idx & 7;
            *(uint4*)&Wa[row * GP + seg * 8] =
                *(const uint4*)&g_Wh[(m0 + row) * CDIM + kc * 64 + seg * 8];
        }
#pragma unroll
        for (int r = 0; r < 4; r++) {
            const int idx = tid + 256 * r;
            const int row = idx >> 3, seg = idx & 7;
            *(uint4*)&Xb[row * GP + seg * 8] =
                *(const uint4*)&g_xhT[((size_t)b * NPIX + n0 + row) * CDIM + kc * 64 + seg * 8];
        }
        __syncthreads();

#pragma unroll
        for (int s = 0; s < 4; s++) {
            uint32_t a[2][4];
#pragma unroll
            for (int i = 0; i < 2; i++) {
                const __half* base = &Wa[(mw + 16 * i + g) * GP + 2 * t + 16 * s];
                a[i][0] = *(const uint32_t*)base;
                a[i][2] = *(const uint32_t*)(base + 8);
                const __half* b8 = base + 8 * GP;
                a[i][1] = *(const uint32_t*)b8;
                a[i][3] = *(const uint32_t*)(b8 + 8);
            }
#pragma unroll
            for (int j = 0; j < 4; j++) {
                const __half* kb = &Xb[(nw + 8 * j + g) * GP + 2 * t + 16 * s];
                const uint32_t b0 = *(const uint32_t*)kb;
                const uint32_t b1 = *(const uint32_t*)(kb + 8);
                mma16816(acc[0][j][0], acc[0][j][1], acc[0][j][2], acc[0][j][3],
                         a[0][0], a[0][1], a[0][2], a[0][3], b0, b1);
                mma16816(acc[1][j][0], acc[1][j][1], acc[1][j][2], acc[1][j][3],
                         a[1][0], a[1][1], a[1][2], a[1][3], b0, b1);
            }
        }
    }

    if (m0 >= 64) {
#pragma unroll
        for (int i = 0; i < 2; i++) {
            const int r0 = mw + 16 * i + g;
            const int r1 = r0 + 8;
            const float bb0 = g_ball[m0 + r0];
            const float bb1 = g_ball[m0 + r1];
            const size_t c0g = (size_t)b * CDIM + (m0 - 64 + r0);
            const size_t c1g = (size_t)b * CDIM + (m0 - 64 + r1);
#pragma unroll
            for (int j = 0; j < 4; j++) {
                const int n = n0 + nw + 8 * j + 2 * t;
                *(__half2*)&g_VhT[c0g * NPIX + n] =
                    __floats2half2_rn(acc[i][j][0] + bb0, acc[i][j][1] + bb0);
                *(__half2*)&g_VhT[c1g * NPIX + n] =
                    __floats2half2_rn(acc[i][j][2] + bb1, acc[i][j][3] + bb1);
            }
        }
    } else {
        __half* Obuf = Xb;
        __syncthreads();
#pragma unroll
        for (int i = 0; i < 2; i++) {
            const int r0 = mw + 16 * i + g;
            const int r1 = r0 + 8;
            const float bb0 = g_ball[r0];
            const float bb1 = g_ball[r1];
#pragma unroll
            for (int j = 0; j < 4; j++) {
                const int n = nw + 8 * j + 2 * t;
                Obuf[n * GP + r0]       = __float2half_rn(acc[i][j][0] + bb0);
                Obuf[(n + 1) * GP + r0] = __float2half_rn(acc[i][j][1] + bb0);
                Obuf[n * GP + r1]       = __float2half_rn(acc[i][j][2] + bb1);
                Obuf[(n + 1) * GP + r1] = __float2half_rn(acc[i][j][3] + bb1);
            }
        }
        __syncthreads();
#pragma unroll
        for (int r = 0; r < 2; r++) {
            const int idx = tid + 256 * r;
            const int n = idx >> 2, seg = idx & 3;
            *(uint4*)&g_Qh[((size_t)b * NPIX + n0 + n) * CQK + seg * 8] =
                *(const uint4*)&Obuf[n * GP + seg * 8];
            *(uint4*)&g_Kh[((size_t)b * NPIX + n0 + n) * CQK + seg * 8] =
                *(const uint4*)&Obuf[n * GP + 32 + seg * 8];
        }
    }
}

// ---------------------------------------------------------------------------
// Flash attention v2: register-resident softmax, redundant warp pairs,
// cp.async double-buffered K/V tiles.
// CTA: 64 queries, 8 warps. Warp w: query rows 16*(w&3).., channels 128*(w>>2)..
// Key tiles of 64.
// ---------------------------------------------------------------------------
#define QTILE 64
#define KTILE 64
#define KP    40   // halves per K row
#define VP    72   // halves per V^T row
// per-buffer: K 64*40*2 = 5120 B, V 256*72*2 = 36864 B -> 41984 B
#define OFS_K0 0
#define OFS_V0 5120
#define OFS_K1 41984
#define OFS_V1 47104
#define ATT_SMEM 83968
#define OBP 66     // Obuf [256 c][66] floats (aliases buffers)

__global__ __launch_bounds__(256, 2) void attn_kernel(
    float* __restrict__ out, const float* __restrict__ gamma)
{
    extern __shared__ __align__(16) char sm[];
    const uint32_t smbase = (uint32_t)__cvta_generic_to_shared(sm);

    const int b   = blockIdx.y;
    const int q0  = blockIdx.x * QTILE;
    const int tid = threadIdx.x;
    const int w   = tid >> 5;
    const int lane = tid & 31;
    const int g = lane >> 2;
    const int t = lane & 3;

    const int qr = 16 * (w & 3);     // query row base for this warp
    const int ch = 128 * (w >> 2);   // channel half base

    const size_t bN = (size_t)b * NPIX;
    const size_t bC = (size_t)b * CDIM;

    // ---- Q fragments straight from global (one time) ----
    uint32_t qa[2][4];
    {
        const __half* r0p = &g_Qh[(bN + q0 + qr + g) * CQK];
        const __half* r8p = r0p + 8 * CQK;
#pragma unroll
        for (int s = 0; s < 2; s++) {
            qa[s][0] = *(const uint32_t*)&r0p[16 * s + 2 * t];
            qa[s][1] = *(const uint32_t*)&r8p[16 * s + 2 * t];
            qa[s][2] = *(const uint32_t*)&r0p[16 * s + 8 + 2 * t];
            qa[s][3] = *(const uint32_t*)&r8p[16 * s + 8 + 2 * t];
        }
    }

    float acc[16][4];
#pragma unroll
    for (int j = 0; j < 16; j++)
#pragma unroll
        for (int k = 0; k < 4; k++) acc[j][k] = 0.f;

    float m0r = -INFINITY, m1r = -INFINITY;
    float l0 = 0.f, l1 = 0.f;

    // tile loader (cp.async, 16B chunks)
    const int krow = tid >> 2, kseg = tid & 3;            // K: 1 chunk/thread
    auto issue_tile = [&](int buf, int m0g) {
        const uint32_t kb = smbase + (buf ? OFS_K1 : OFS_K0);
        const uint32_t vb = smbase + (buf ? OFS_V1 : OFS_V0);
        cpa16(kb + krow * (KP * 2) + kseg * 16,
              &g_Kh[(bN + m0g + krow) * CQK + kseg * 8]);
#pragma unroll
        for (int it = 0; it < 8; it++) {
            const int idx = tid + 256 * it;
            const int c = idx >> 3, seg = idx & 7;
            cpa16(vb + c * (VP * 2) + seg * 16,
                  &g_VhT[(bC + c) * NPIX + m0g + seg * 8]);
        }
        cpa_commit();
    };

    issue_tile(0, 0);

    for (int kt = 0; kt < NPIX / KTILE; kt++) {
        const int buf = kt & 1;
        cpa_wait0();
        __syncthreads();                       // tile ready; prev reads done
        if (kt + 1 < NPIX / KTILE)
            issue_tile(buf ^ 1, (kt + 1) * KTILE);

        const __half* Ks  = (const __half*)(sm + (buf ? OFS_K1 : OFS_K0));
        const __half* VsT = (const __half*)(sm + (buf ? OFS_V1 : OFS_V0));

        // ---- S = Q K^T : S[16][64] in registers ----
        float sc[8][4];
#pragma unroll
        for (int j = 0; j < 8; j++) {
            float c0 = 0.f, c1 = 0.f, c2 = 0.f, c3 = 0.f;
#pragma unroll
            for (int s = 0; s < 2; s++) {
                const __half* kb = &Ks[(8 * j + g) * KP + 2 * t + 16 * s];
                const uint32_t b0 = *(const uint32_t*)kb;
                const uint32_t b1 = *(const uint32_t*)(kb + 8);
                mma16816(c0, c1, c2, c3, qa[s][0], qa[s][1], qa[s][2], qa[s][3], b0, b1);
            }
            sc[j][0] = c0; sc[j][1] = c1; sc[j][2] = c2; sc[j][3] = c3;
        }

        // ---- online softmax in registers (quad shuffles) ----
        float mx0 = -INFINITY, mx1 = -INFINITY;
#pragma unroll
        for (int j = 0; j < 8; j++) {
            mx0 = fmaxf(mx0, fmaxf(sc[j][0], sc[j][1]));
            mx1 = fmaxf(mx1, fmaxf(sc[j][2], sc[j][3]));
        }
        mx0 = fmaxf(mx0, __shfl_xor_sync(0xffffffff, mx0, 1));
        mx0 = fmaxf(mx0, __shfl_xor_sync(0xffffffff, mx0, 2));
        mx1 = fmaxf(mx1, __shfl_xor_sync(0xffffffff, mx1, 1));
        mx1 = fmaxf(mx1, __shfl_xor_sync(0xffffffff, mx1, 2));

        const float mn0 = fmaxf(m0r, mx0);
        const float mn1 = fmaxf(m1r, mx1);
        const float al0 = __expf(m0r - mn0);
        const float al1 = __expf(m1r - mn1);
        m0r = mn0; m1r = mn1;

        uint32_t pa[4][4];
        float s0 = 0.f, s1 = 0.f;
#pragma unroll
        for (int s = 0; s < 4; s++) {
            {
                const int j = 2 * s;
                const float p00 = __expf(sc[j][0] - mn0);
                const float p01 = __expf(sc[j][1] - mn0);
                const float p10 = __expf(sc[j][2] - mn1);
                const float p11 = __expf(sc[j][3] - mn1);
                s0 += p00 + p01; s1 += p10 + p11;
                pa[s][0] = h2_as_u32(__floats2half2_rn(p00, p01));
                pa[s][1] = h2_as_u32(__floats2half2_rn(p10, p11));
            }
            {
                const int j = 2 * s + 1;
                const float p00 = __expf(sc[j][0] - mn0);
                const float p01 = __expf(sc[j][1] - mn0);
                const float p10 = __expf(sc[j][2] - mn1);
                const float p11 = __expf(sc[j][3] - mn1);
                s0 += p00 + p01; s1 += p10 + p11;
                pa[s][2] = h2_as_u32(__floats2half2_rn(p00, p01));
                pa[s][3] = h2_as_u32(__floats2half2_rn(p10, p11));
            }
        }
        s0 += __shfl_xor_sync(0xffffffff, s0, 1);
        s0 += __shfl_xor_sync(0xffffffff, s0, 2);
        s1 += __shfl_xor_sync(0xffffffff, s1, 1);
        s1 += __shfl_xor_sync(0xffffffff, s1, 2);
        l0 = l0 * al0 + s0;
        l1 = l1 * al1 + s1;

        // ---- rescale accumulators ----
#pragma unroll
        for (int j = 0; j < 16; j++) {
            acc[j][0] *= al0; acc[j][1] *= al0;
            acc[j][2] *= al1; acc[j][3] *= al1;
        }

        // ---- O += P V (P fragments from registers) ----
#pragma unroll
        for (int s = 0; s < 4; s++) {
#pragma unroll
            for (int jj = 0; jj < 16; jj++) {
                const __half* vb = &VsT[(ch + 8 * jj + g) * VP + 2 * t + 16 * s];
                const uint32_t b0 = *(const uint32_t*)vb;
                const uint32_t b1 = *(const uint32_t*)(vb + 8);
                mma16816(acc[jj][0], acc[jj][1], acc[jj][2], acc[jj][3],
                         pa[s][0], pa[s][1], pa[s][2], pa[s][3], b0, b1);
            }
        }
    }

    // ---- epilogue: scale, transpose via smem, coalesced store ----
    const float gamma0 = gamma[0];
    const float inv0 = gamma0 / l0;
    const float inv1 = gamma0 / l1;

    float* Obuf = (float*)sm;   // [256 c][OBP]
    __syncthreads();            // everyone done reading V buffers
#pragma unroll
    for (int jj = 0; jj < 16; jj++) {
        const int c = ch + 8 * jj + 2 * t;
        const int r0 = qr + g;
        const int r1 = r0 + 8;
        Obuf[c * OBP + r0]       = acc[jj][0] * inv0;
        Obuf[(c + 1) * OBP + r0] = acc[jj][1] * inv0;
        Obuf[c * OBP + r1]       = acc[jj][2] * inv1;
        Obuf[(c + 1) * OBP + r1] = acc[jj][3] * inv1;
    }
    __syncthreads();
#pragma unroll
    for (int it = 0; it < 64; it++) {
        const int idx = tid + 256 * it;
        const int c = idx >> 6, q = idx & 63;
        out[(bC + c) * NPIX + q0 + q] = Obuf[c * OBP + q];
    }
}

// ---------------------------------------------------------------------------
// Inputs: x, Wq, bq, Wk, bk, Wv, bv, gamma. Output: float32 [B,C,H,W].
// ---------------------------------------------------------------------------
extern "C" void kernel_launch(void* const* d_in, const int* in_sizes, int n_in,
                              void* d_out, int out_size)
{
    const float* x     = (const float*)d_in[0];
    const float* Wq    = (const float*)d_in[1];
    const float* bq    = (const float*)d_in[2];
    const float* Wk    = (const float*)d_in[3];
    const float* bk    = (const float*)d_in[4];
    const float* Wv    = (const float*)d_in[5];
    const float* bv    = (const float*)d_in[6];
    const float* gamma = (const float*)d_in[7];
    float* out = (float*)d_out;

    cudaFuncSetAttribute(attn_kernel,
                         cudaFuncAttributeMaxDynamicSharedMemorySize, ATT_SMEM);

    wconv_kernel<<<80, 256>>>(Wq, bq, Wk, bk, Wv, bv);
    xconv_kernel<<<dim3(NPIX / 32, CDIM / 32, BATCH), 256>>>(x);
    proj_gemm_kernel<<<dim3(NPIX / 128, BATCH, 5), 256>>>();
    attn_kernel<<<dim3(NPIX / QTILE, BATCH), 256, ATT_SMEM>>>(out, gamma);
}